// round 12
// baseline (speedup 1.0000x reference)
#include <cuda_runtime.h>

#define BB   4
#define NN   2048
#define DIN  128
#define DOUT 128      // H*HD
#define HH   4
#define HD   32
#define NWRD (NN/32)  // 64 words per adjT row

#define NSPLIT 8
#define JCHUNK (NN/NSPLIT)   // 256 j per warp
#define TJS    32            // j tile per warp per stage

#define LOG2E 1.4426950408889634f

// ---------------- scratch (static device globals; no allocation) -------------
__device__ float    g_h [BB*NN*DOUT];   // 4 MB   h = x @ W^T
__device__ float    g_ei[BB*NN*HH];     // 128 KB (pre-scaled by log2e)
__device__ float    g_ej[BB*NN*HH];     // 128 KB (pre-scaled by log2e)
__device__ unsigned g_adjT[NN*NWRD];    // 512 KB, bit l of word [j][iw] = adj[iw*32+l][j]

// ---------------- kernel 1: h = x @ W^T + fused ei/ej ------------------------
__global__ void __launch_bounds__(256) gemm_h_kernel(const float* __restrict__ x,
                                                     const float* __restrict__ W,
                                                     const float* __restrict__ a) {
    __shared__ __align__(16) float x_s[64][36];
    __shared__ __align__(16) float w_s[32][132];

    const int tid = threadIdx.x;
    const int cg  = tid & 31;
    const int rg  = tid >> 5;
    const int row0 = blockIdx.x * 64;

    float acc[8][4];
    #pragma unroll
    for (int r = 0; r < 8; ++r)
        #pragma unroll
        for (int c = 0; c < 4; ++c) acc[r][c] = 0.f;

    for (int k0 = 0; k0 < DIN; k0 += 32) {
        #pragma unroll
        for (int it = 0; it < 2; ++it) {
            int f = tid + it * 256;
            int r = f >> 3, q = f & 7;
            float4 v = *(const float4*)(x + (size_t)(row0 + r) * DIN + k0 + q * 4);
            *(float4*)&x_s[r][q * 4] = v;
        }
        {
            int c = tid >> 1, half = tid & 1;
            const float* wp = W + (size_t)c * DIN + k0 + half * 16;
            #pragma unroll
            for (int kk = 0; kk < 16; ++kk)
                w_s[half * 16 + kk][c] = wp[kk];
        }
        __syncthreads();
        #pragma unroll
        for (int k = 0; k < 32; ++k) {
            float4 wv = *(const float4*)&w_s[k][cg * 4];
            #pragma unroll
            for (int r = 0; r < 8; ++r) {
                float xv = x_s[rg * 8 + r][k];
                acc[r][0] += xv * wv.x;
                acc[r][1] += xv * wv.y;
                acc[r][2] += xv * wv.z;
                acc[r][3] += xv * wv.w;
            }
        }
        __syncthreads();
    }

    // store h
    #pragma unroll
    for (int r = 0; r < 8; ++r) {
        float4 v = make_float4(acc[r][0], acc[r][1], acc[r][2], acc[r][3]);
        *(float4*)(g_h + (size_t)(row0 + rg * 8 + r) * DOUT + cg * 4) = v;
    }

    // fused ei/ej: this thread holds rows rg*8..+7, head = cg>>3, cols (cg&7)*4..+3
    const int head = cg >> 3;
    const int c0   = (cg & 7) * 4;
    float a1v[4], a2v[4];
    #pragma unroll
    for (int k = 0; k < 4; ++k) {
        a1v[k] = a[head * 2 * HD + c0 + k];
        a2v[k] = a[head * 2 * HD + HD + c0 + k];
    }
    #pragma unroll
    for (int r = 0; r < 8; ++r) {
        float p1 = acc[r][0] * a1v[0] + acc[r][1] * a1v[1]
                 + acc[r][2] * a1v[2] + acc[r][3] * a1v[3];
        float p2 = acc[r][0] * a2v[0] + acc[r][1] * a2v[1]
                 + acc[r][2] * a2v[2] + acc[r][3] * a2v[3];
        p1 += __shfl_down_sync(0xffffffffu, p1, 4, 8);
        p1 += __shfl_down_sync(0xffffffffu, p1, 2, 8);
        p1 += __shfl_down_sync(0xffffffffu, p1, 1, 8);
        p2 += __shfl_down_sync(0xffffffffu, p2, 4, 8);
        p2 += __shfl_down_sync(0xffffffffu, p2, 2, 8);
        p2 += __shfl_down_sync(0xffffffffu, p2, 1, 8);
        if ((cg & 7) == 0) {
            int bn = row0 + rg * 8 + r;
            g_ei[bn * HH + head] = p1 * LOG2E;   // pre-scale for ex2.approx
            g_ej[bn * HH + head] = p2 * LOG2E;
        }
    }
}

// ---------------- kernel 2: pack adj transposed into bitmask -----------------
__global__ void adjt_kernel(const int* __restrict__ adj) {
    __shared__ int s[32][33];
    const int tx = threadIdx.x, ty = threadIdx.y;
    const int j0 = blockIdx.x * 32, i0 = blockIdx.y * 32;
    s[ty][tx] = adj[(size_t)(i0 + ty) * NN + j0 + tx];
    __syncthreads();
    int val = s[tx][ty];
    unsigned m = __ballot_sync(0xffffffffu, val != 0);
    if (tx == 0) g_adjT[(size_t)(j0 + ty) * NWRD + (i0 >> 5)] = m;
}

// ---------------- kernel 3: fused masked-softmax attention -------------------
// block = 256 thr = 8 warps. Warp w owns j-split [w*256,(w+1)*256), covers all
// 64 i of the block (2 i-groups per lane). Warp-private tiles, no in-loop
// barriers. Cross-warp partial reduction via smem f32x2 adds at the end.
__global__ void __launch_bounds__(256, 2) gat_main_kernel(float* __restrict__ out) {
    __shared__ __align__(16) union {
        struct {
            float    h  [NSPLIT][TJS][HD];   // 32 KB
            float    ej [NSPLIT][TJS];       // 1 KB
            unsigned adj[NSPLIT][TJS][2];    // 2 KB
        } st;
        unsigned long long red[4][64][17];   // 34 KB (aliased, post-loop)
    } sm;

    const int b   = blockIdx.z;
    const int hh  = blockIdx.y;
    const int i0  = blockIdx.x * 64;
    const int w   = threadIdx.x >> 5;
    const int l   = threadIdx.x & 31;
    const int iw0 = i0 >> 5;
    const unsigned lanebit = 1u << l;

    const float ei0 = g_ei[((size_t)b * NN + i0 + l)      * HH + hh];
    const float ei1 = g_ei[((size_t)b * NN + i0 + 32 + l) * HH + hh];

    unsigned long long acc0[16], acc1[16];
    #pragma unroll
    for (int p = 0; p < 16; ++p) { acc0[p] = 0ull; acc1[p] = 0ull; }
    float denom0 = 0.f, denom1 = 0.f;

    const unsigned hbase  = (unsigned)__cvta_generic_to_shared(&sm.st.h[w][0][0]);
    const int jbase = w * JCHUNK;

    for (int js = 0; js < JCHUNK; js += TJS) {
        const int jg = jbase + js;
        __syncwarp();   // all lanes done reading previous tile

        // --- stage via cp.async (warp-private tile) ---
        {
            const char* gsrc = (const char*)(g_h + ((size_t)b * NN + jg) * DOUT + hh * HD);
            #pragma unroll
            for (int it = 0; it < 8; ++it) {
                int t = l + it * 32;
                int row = t >> 3, q = t & 7;
                const char* gp = gsrc + (size_t)row * (DOUT * 4) + q * 16;
                unsigned sp = hbase + (unsigned)(row * (HD * 4) + q * 16);
                asm volatile("cp.async.ca.shared.global [%0], [%1], 16;"
                             :: "r"(sp), "l"(gp));
            }
            const char* ep = (const char*)(g_ej + ((size_t)b * NN + jg + l) * HH + hh);
            unsigned esp = (unsigned)__cvta_generic_to_shared(&sm.st.ej[w][l]);
            asm volatile("cp.async.ca.shared.global [%0], [%1], 4;"
                         :: "r"(esp), "l"(ep));
            const char* ap = (const char*)(g_adjT + (size_t)(jg + l) * NWRD + iw0);
            unsigned asp = (unsigned)__cvta_generic_to_shared(&sm.st.adj[w][l][0]);
            asm volatile("cp.async.ca.shared.global [%0], [%1], 8;"
                         :: "r"(asp), "l"(ap));
            asm volatile("cp.async.commit_group;");
            asm volatile("cp.async.wait_group 0;" ::: "memory");
            __syncwarp();
        }

        // --- consume tile ---
        #pragma unroll 2
        for (int jj = 0; jj < TJS; ++jj) {
            float ejv = sm.st.ej[w][jj];                    // broadcast LDS
            unsigned m0 = sm.st.adj[w][jj][0];              // broadcast LDS (v2)
            unsigned m1 = sm.st.adj[w][jj][1];
            float t0 = ei0 + ejv;
            float t1 = ei1 + ejv;
            float lk0 = fmaxf(t0, 0.2f * t0);
            float lk1 = fmaxf(t1, 0.2f * t1);
            float e0, e1;
            asm("ex2.approx.f32 %0, %1;" : "=f"(e0) : "f"(lk0));
            asm("ex2.approx.f32 %0, %1;" : "=f"(e1) : "f"(lk1));
            float w0 = (m0 & lanebit) ? e0 : 0.f;
            float w1 = (m1 & lanebit) ? e1 : 0.f;
            denom0 += w0;
            denom1 += w1;
            unsigned long long w20, w21;
            asm("mov.b64 %0, {%1, %1};" : "=l"(w20) : "f"(w0));
            asm("mov.b64 %0, {%1, %1};" : "=l"(w21) : "f"(w1));
            unsigned addr = hbase + (unsigned)(jj * (HD * 4));
            #pragma unroll
            for (int p = 0; p < 8; ++p) {
                unsigned long long a0, a1;
                asm volatile("ld.shared.v2.b64 {%0, %1}, [%2];"
                             : "=l"(a0), "=l"(a1) : "r"(addr + p * 16));
                asm("fma.rn.f32x2 %0, %1, %2, %0;" : "+l"(acc0[2*p])   : "l"(w20), "l"(a0));
                asm("fma.rn.f32x2 %0, %1, %2, %0;" : "+l"(acc0[2*p+1]) : "l"(w20), "l"(a1));
                asm("fma.rn.f32x2 %0, %1, %2, %0;" : "+l"(acc1[2*p])   : "l"(w21), "l"(a0));
                asm("fma.rn.f32x2 %0, %1, %2, %0;" : "+l"(acc1[2*p+1]) : "l"(w21), "l"(a1));
            }
        }
    }

    // ---------------- cross-warp tree reduction (3 rounds) -------------------
    #define WRITE_P(BUFI)                                                        \
        do {                                                                     \
            unsigned long long* d0 = &sm.red[BUFI][l][0];                        \
            unsigned long long* d1 = &sm.red[BUFI][32 + l][0];                   \
            _Pragma("unroll")                                                    \
            for (int p = 0; p < 16; ++p) { d0[p] = acc0[p]; d1[p] = acc1[p]; }   \
            ((float*)&d0[16])[0] = denom0;                                       \
            ((float*)&d1[16])[0] = denom1;                                       \
        } while (0)
    #define ADD_P(BUFI)                                                         \
        do {                                                                    \
            const unsigned long long* s0 = &sm.red[BUFI][l][0];                 \
            const unsigned long long* s1 = &sm.red[BUFI][32 + l][0];            \
            _Pragma("unroll")                                                   \
            for (int p = 0; p < 16; ++p) {                                      \
                asm("add.rn.f32x2 %0, %0, %1;" : "+l"(acc0[p]) : "l"(s0[p]));   \
                asm("add.rn.f32x2 %0, %0, %1;" : "+l"(acc1[p]) : "l"(s1[p]));   \
            }                                                                   \
            denom0 += ((const float*)&s0[16])[0];                               \
            denom1 += ((const float*)&s1[16])[0];                               \
        } while (0)

    __syncthreads();
    if (w & 1) WRITE_P(w >> 1);
    __syncthreads();
    if (!(w & 1)) ADD_P(w >> 1);
    __syncthreads();
    if (w == 2) WRITE_P(0);
    if (w == 6) WRITE_P(1);
    __syncthreads();
    if (w == 0) ADD_P(0);
    if (w == 4) ADD_P(1);
    __syncthreads();
    if (w == 4) WRITE_P(0);
    __syncthreads();

    if (w == 0) {
        ADD_P(0);
        const float inv0 = 1.0f / denom0;
        const float inv1 = 1.0f / denom1;
        float* dst0 = out + ((size_t)b * NN + i0 + l)      * DOUT + hh * HD;
        float* dst1 = out + ((size_t)b * NN + i0 + 32 + l) * DOUT + hh * HD;
        #pragma unroll
        for (int p = 0; p < 8; ++p) {
            float x0, y0, x1, y1;
            asm("mov.b64 {%0, %1}, %2;" : "=f"(x0), "=f"(y0) : "l"(acc0[2*p]));
            asm("mov.b64 {%0, %1}, %2;" : "=f"(x1), "=f"(y1) : "l"(acc0[2*p+1]));
            *(float4*)(dst0 + p * 4) = make_float4(x0*inv0, y0*inv0, x1*inv0, y1*inv0);
            asm("mov.b64 {%0, %1}, %2;" : "=f"(x0), "=f"(y0) : "l"(acc1[2*p]));
            asm("mov.b64 {%0, %1}, %2;" : "=f"(x1), "=f"(y1) : "l"(acc1[2*p+1]));
            *(float4*)(dst1 + p * 4) = make_float4(x0*inv1, y0*inv1, x1*inv1, y1*inv1);
        }
    }
    #undef WRITE_P
    #undef ADD_P
}

// ---------------- launch ------------------------------------------------------
extern "C" void kernel_launch(void* const* d_in, const int* in_sizes, int n_in,
                              void* d_out, int out_size) {
    const float* x   = (const float*)d_in[0];   // (B,N,DIN) f32
    const int*   adj = (const int*)  d_in[1];   // (N,N) i32
    const float* W   = (const float*)d_in[2];   // (H*HD, DIN) f32
    const float* a   = (const float*)d_in[3];   // (H, 2*HD, 1) f32
    float* out = (float*)d_out;                 // (B,N,H*HD) f32

    gemm_h_kernel<<<(BB * NN) / 64, 256>>>(x, W, a);
    adjt_kernel<<<dim3(NN / 32, NN / 32), dim3(32, 32)>>>(adj);
    gat_main_kernel<<<dim3(NN / 64, HH, BB), 256>>>(out);
}

// round 13
// speedup vs baseline: 1.0727x; 1.0727x over previous
#include <cuda_runtime.h>

#define BB   4
#define NN   2048
#define DIN  128
#define DOUT 128      // H*HD
#define HH   4
#define HD   32
#define NWRD (NN/32)  // 64 words per adjT row

#define NSPLIT 8
#define JCHUNK (NN/NSPLIT)   // 256 j per warp
#define TJS    16            // j tile per warp per stage (double-buffered)
#define NSTAGE (JCHUNK/TJS)  // 16 stages

#define LOG2E 1.4426950408889634f

// ---------------- scratch (static device globals; no allocation) -------------
__device__ float    g_h [BB*NN*DOUT];   // 4 MB   h = x @ W^T
__device__ float    g_ei[BB*NN*HH];     // 128 KB (pre-scaled by log2e)
__device__ float    g_ej[BB*NN*HH];     // 128 KB (pre-scaled by log2e)
__device__ unsigned g_adjT[NN*NWRD];    // 512 KB, bit l of word [j][iw] = adj[iw*32+l][j]

// ---------------- kernel 1: h = x @ W^T + fused ei/ej ------------------------
// 32-row tiles, 128 threads -> 256 blocks (was 128) for latency hiding.
__global__ void __launch_bounds__(128) gemm_h_kernel(const float* __restrict__ x,
                                                     const float* __restrict__ W,
                                                     const float* __restrict__ a) {
    __shared__ __align__(16) float x_s[32][36];
    __shared__ __align__(16) float w_s[32][132];

    const int tid = threadIdx.x;
    const int cg  = tid & 31;       // cols cg*4 .. cg*4+3
    const int rg  = tid >> 5;       // rows rg*8 .. rg*8+7 (4 warps)
    const int row0 = blockIdx.x * 32;

    float acc[8][4];
    #pragma unroll
    for (int r = 0; r < 8; ++r)
        #pragma unroll
        for (int c = 0; c < 4; ++c) acc[r][c] = 0.f;

    for (int k0 = 0; k0 < DIN; k0 += 32) {
        // stage x tile (32 rows x 32 k) = 256 float4, 128 threads -> 2 iters
        #pragma unroll
        for (int it = 0; it < 2; ++it) {
            int f = tid + it * 128;
            int r = f >> 3, q = f & 7;
            float4 v = *(const float4*)(x + (size_t)(row0 + r) * DIN + k0 + q * 4);
            *(float4*)&x_s[r][q * 4] = v;
        }
        // stage W tile transposed: thread c loads W[c][k0..k0+31]
        {
            const float* wp = W + (size_t)tid * DIN + k0;
            #pragma unroll
            for (int kk = 0; kk < 32; kk += 4) {
                float4 v = *(const float4*)(wp + kk);
                w_s[kk + 0][tid] = v.x;
                w_s[kk + 1][tid] = v.y;
                w_s[kk + 2][tid] = v.z;
                w_s[kk + 3][tid] = v.w;
            }
        }
        __syncthreads();
        #pragma unroll
        for (int k = 0; k < 32; ++k) {
            float4 wv = *(const float4*)&w_s[k][cg * 4];
            #pragma unroll
            for (int r = 0; r < 8; ++r) {
                float xv = x_s[rg * 8 + r][k];
                acc[r][0] += xv * wv.x;
                acc[r][1] += xv * wv.y;
                acc[r][2] += xv * wv.z;
                acc[r][3] += xv * wv.w;
            }
        }
        __syncthreads();
    }

    // store h
    #pragma unroll
    for (int r = 0; r < 8; ++r) {
        float4 v = make_float4(acc[r][0], acc[r][1], acc[r][2], acc[r][3]);
        *(float4*)(g_h + (size_t)(row0 + rg * 8 + r) * DOUT + cg * 4) = v;
    }

    // fused ei/ej: head = cg>>3, cols (cg&7)*4..+3, reduce over 8-lane groups
    const int head = cg >> 3;
    const int c0   = (cg & 7) * 4;
    float a1v[4], a2v[4];
    #pragma unroll
    for (int k = 0; k < 4; ++k) {
        a1v[k] = a[head * 2 * HD + c0 + k];
        a2v[k] = a[head * 2 * HD + HD + c0 + k];
    }
    #pragma unroll
    for (int r = 0; r < 8; ++r) {
        float p1 = acc[r][0] * a1v[0] + acc[r][1] * a1v[1]
                 + acc[r][2] * a1v[2] + acc[r][3] * a1v[3];
        float p2 = acc[r][0] * a2v[0] + acc[r][1] * a2v[1]
                 + acc[r][2] * a2v[2] + acc[r][3] * a2v[3];
        p1 += __shfl_down_sync(0xffffffffu, p1, 4, 8);
        p1 += __shfl_down_sync(0xffffffffu, p1, 2, 8);
        p1 += __shfl_down_sync(0xffffffffu, p1, 1, 8);
        p2 += __shfl_down_sync(0xffffffffu, p2, 4, 8);
        p2 += __shfl_down_sync(0xffffffffu, p2, 2, 8);
        p2 += __shfl_down_sync(0xffffffffu, p2, 1, 8);
        if ((cg & 7) == 0) {
            int bn = row0 + rg * 8 + r;
            g_ei[bn * HH + head] = p1 * LOG2E;
            g_ej[bn * HH + head] = p2 * LOG2E;
        }
    }
}

// ---------------- kernel 2: pack adj transposed into bitmask -----------------
__global__ void adjt_kernel(const int* __restrict__ adj) {
    __shared__ int s[32][33];
    const int tx = threadIdx.x, ty = threadIdx.y;
    const int j0 = blockIdx.x * 32, i0 = blockIdx.y * 32;
    s[ty][tx] = adj[(size_t)(i0 + ty) * NN + j0 + tx];
    __syncthreads();
    int val = s[tx][ty];
    unsigned m = __ballot_sync(0xffffffffu, val != 0);
    if (tx == 0) g_adjT[(size_t)(j0 + ty) * NWRD + (i0 >> 5)] = m;
}

// ---------------- kernel 3: fused masked-softmax attention -------------------
// block = 256 thr = 8 warps. Warp w owns j-split [w*256,(w+1)*256), covers all
// 64 i (2 i-groups per lane). Warp-private DOUBLE-BUFFERED cp.async tiles —
// prefetch of tile s+1 overlaps consumption of tile s. No in-loop barriers.
__global__ void __launch_bounds__(256, 2) gat_main_kernel(float* __restrict__ out) {
    __shared__ __align__(16) union {
        struct {
            float    h  [NSPLIT][2][TJS][HD];   // 32 KB
            float    ej [NSPLIT][2][TJS];       // 1 KB
            unsigned adj[NSPLIT][2][TJS][2];    // 2 KB
        } st;
        unsigned long long red[4][64][17];      // 34 KB (aliased, post-loop)
    } sm;

    const int b   = blockIdx.z;
    const int hh  = blockIdx.y;
    const int i0  = blockIdx.x * 64;
    const int w   = threadIdx.x >> 5;
    const int l   = threadIdx.x & 31;
    const int iw0 = i0 >> 5;
    const unsigned lanebit = 1u << l;

    const float ei0 = g_ei[((size_t)b * NN + i0 + l)      * HH + hh];
    const float ei1 = g_ei[((size_t)b * NN + i0 + 32 + l) * HH + hh];

    unsigned long long acc0[16], acc1[16];
    #pragma unroll
    for (int p = 0; p < 16; ++p) { acc0[p] = 0ull; acc1[p] = 0ull; }
    float denom0 = 0.f, denom1 = 0.f;

    const int jbase = w * JCHUNK;
    const unsigned hb[2]  = {
        (unsigned)__cvta_generic_to_shared(&sm.st.h[w][0][0][0]),
        (unsigned)__cvta_generic_to_shared(&sm.st.h[w][1][0][0]) };
    const unsigned ejb[2] = {
        (unsigned)__cvta_generic_to_shared(&sm.st.ej[w][0][0]),
        (unsigned)__cvta_generic_to_shared(&sm.st.ej[w][1][0]) };
    const unsigned adb[2] = {
        (unsigned)__cvta_generic_to_shared(&sm.st.adj[w][0][0][0]),
        (unsigned)__cvta_generic_to_shared(&sm.st.adj[w][1][0][0]) };

    // prefetch helper (macro to keep everything in registers)
    #define PREFETCH(BUF, JG)                                                     \
        do {                                                                      \
            const char* gsrc = (const char*)(g_h + ((size_t)b * NN + (JG)) * DOUT \
                                             + hh * HD);                          \
            _Pragma("unroll")                                                     \
            for (int it = 0; it < 4; ++it) {                                      \
                int t = l + it * 32;                                              \
                int row = t >> 3, q = t & 7;                                      \
                const char* gp = gsrc + (size_t)row * (DOUT * 4) + q * 16;        \
                unsigned sp = hb[BUF] + (unsigned)(row * (HD * 4) + q * 16);      \
                asm volatile("cp.async.ca.shared.global [%0], [%1], 16;"          \
                             :: "r"(sp), "l"(gp));                                \
            }                                                                     \
            if (l < TJS) {                                                        \
                const char* ep = (const char*)(g_ej                               \
                    + ((size_t)b * NN + (JG) + l) * HH + hh);                     \
                asm volatile("cp.async.ca.shared.global [%0], [%1], 4;"           \
                             :: "r"(ejb[BUF] + l * 4u), "l"(ep));                 \
                const char* ap = (const char*)(g_adjT                             \
                    + (size_t)((JG) + l) * NWRD + iw0);                           \
                asm volatile("cp.async.ca.shared.global [%0], [%1], 8;"           \
                             :: "r"(adb[BUF] + l * 8u), "l"(ap));                 \
            }                                                                     \
            asm volatile("cp.async.commit_group;");                               \
        } while (0)

    PREFETCH(0, jbase);

    for (int st = 0; st < NSTAGE; ++st) {
        const int buf = st & 1;
        if (st + 1 < NSTAGE) {
            PREFETCH(1 - buf, jbase + (st + 1) * TJS);
            asm volatile("cp.async.wait_group 1;" ::: "memory");
        } else {
            asm volatile("cp.async.wait_group 0;" ::: "memory");
        }
        __syncwarp();

        const float*    ejp  = &sm.st.ej[w][buf][0];
        const unsigned* adjp = &sm.st.adj[w][buf][0][0];
        const unsigned  hbase = hb[buf];

        #pragma unroll 4
        for (int jj = 0; jj < TJS; ++jj) {
            float ejv = ejp[jj];                            // broadcast LDS
            unsigned m0 = adjp[jj * 2];                     // broadcast LDS.64
            unsigned m1 = adjp[jj * 2 + 1];
            float t0 = ei0 + ejv;
            float t1 = ei1 + ejv;
            float lk0 = fmaxf(t0, 0.2f * t0);
            float lk1 = fmaxf(t1, 0.2f * t1);
            float e0, e1;
            asm("ex2.approx.f32 %0, %1;" : "=f"(e0) : "f"(lk0));
            asm("ex2.approx.f32 %0, %1;" : "=f"(e1) : "f"(lk1));
            float w0 = (m0 & lanebit) ? e0 : 0.f;
            float w1 = (m1 & lanebit) ? e1 : 0.f;
            denom0 += w0;
            denom1 += w1;
            unsigned long long w20, w21;
            asm("mov.b64 %0, {%1, %1};" : "=l"(w20) : "f"(w0));
            asm("mov.b64 %0, {%1, %1};" : "=l"(w21) : "f"(w1));
            unsigned addr = hbase + (unsigned)(jj * (HD * 4));
            #pragma unroll
            for (int p = 0; p < 8; ++p) {
                unsigned long long a0, a1;
                asm volatile("ld.shared.v2.b64 {%0, %1}, [%2];"
                             : "=l"(a0), "=l"(a1) : "r"(addr + p * 16));
                asm("fma.rn.f32x2 %0, %1, %2, %0;" : "+l"(acc0[2*p])   : "l"(w20), "l"(a0));
                asm("fma.rn.f32x2 %0, %1, %2, %0;" : "+l"(acc0[2*p+1]) : "l"(w20), "l"(a1));
                asm("fma.rn.f32x2 %0, %1, %2, %0;" : "+l"(acc1[2*p])   : "l"(w21), "l"(a0));
                asm("fma.rn.f32x2 %0, %1, %2, %0;" : "+l"(acc1[2*p+1]) : "l"(w21), "l"(a1));
            }
        }
        __syncwarp();   // all lanes done with buf before it is refilled
    }
    #undef PREFETCH

    // ---------------- cross-warp tree reduction (3 rounds) -------------------
    #define WRITE_P(BUFI)                                                        \
        do {                                                                     \
            unsigned long long* d0 = &sm.red[BUFI][l][0];                        \
            unsigned long long* d1 = &sm.red[BUFI][32 + l][0];                   \
            _Pragma("unroll")                                                    \
            for (int p = 0; p < 16; ++p) { d0[p] = acc0[p]; d1[p] = acc1[p]; }   \
            ((float*)&d0[16])[0] = denom0;                                       \
            ((float*)&d1[16])[0] = denom1;                                       \
        } while (0)
    #define ADD_P(BUFI)                                                         \
        do {                                                                    \
            const unsigned long long* s0 = &sm.red[BUFI][l][0];                 \
            const unsigned long long* s1 = &sm.red[BUFI][32 + l][0];            \
            _Pragma("unroll")                                                   \
            for (int p = 0; p < 16; ++p) {                                      \
                asm("add.rn.f32x2 %0, %0, %1;" : "+l"(acc0[p]) : "l"(s0[p]));   \
                asm("add.rn.f32x2 %0, %0, %1;" : "+l"(acc1[p]) : "l"(s1[p]));   \
            }                                                                   \
            denom0 += ((const float*)&s0[16])[0];                               \
            denom1 += ((const float*)&s1[16])[0];                               \
        } while (0)

    __syncthreads();
    if (w & 1) WRITE_P(w >> 1);
    __syncthreads();
    if (!(w & 1)) ADD_P(w >> 1);
    __syncthreads();
    if (w == 2) WRITE_P(0);
    if (w == 6) WRITE_P(1);
    __syncthreads();
    if (w == 0) ADD_P(0);
    if (w == 4) ADD_P(1);
    __syncthreads();
    if (w == 4) WRITE_P(0);
    __syncthreads();

    if (w == 0) {
        ADD_P(0);
        const float inv0 = 1.0f / denom0;
        const float inv1 = 1.0f / denom1;
        float* dst0 = out + ((size_t)b * NN + i0 + l)      * DOUT + hh * HD;
        float* dst1 = out + ((size_t)b * NN + i0 + 32 + l) * DOUT + hh * HD;
        #pragma unroll
        for (int p = 0; p < 8; ++p) {
            float x0, y0, x1, y1;
            asm("mov.b64 {%0, %1}, %2;" : "=f"(x0), "=f"(y0) : "l"(acc0[2*p]));
            asm("mov.b64 {%0, %1}, %2;" : "=f"(x1), "=f"(y1) : "l"(acc0[2*p+1]));
            *(float4*)(dst0 + p * 4) = make_float4(x0*inv0, y0*inv0, x1*inv0, y1*inv0);
            asm("mov.b64 {%0, %1}, %2;" : "=f"(x0), "=f"(y0) : "l"(acc1[2*p]));
            asm("mov.b64 {%0, %1}, %2;" : "=f"(x1), "=f"(y1) : "l"(acc1[2*p+1]));
            *(float4*)(dst1 + p * 4) = make_float4(x0*inv1, y0*inv1, x1*inv1, y1*inv1);
        }
    }
    #undef WRITE_P
    #undef ADD_P
}

// ---------------- launch ------------------------------------------------------
extern "C" void kernel_launch(void* const* d_in, const int* in_sizes, int n_in,
                              void* d_out, int out_size) {
    const float* x   = (const float*)d_in[0];   // (B,N,DIN) f32
    const int*   adj = (const int*)  d_in[1];   // (N,N) i32
    const float* W   = (const float*)d_in[2];   // (H*HD, DIN) f32
    const float* a   = (const float*)d_in[3];   // (H, 2*HD, 1) f32
    float* out = (float*)d_out;                 // (B,N,H*HD) f32

    gemm_h_kernel<<<(BB * NN) / 32, 128>>>(x, W, a);
    adjt_kernel<<<dim3(NN / 32, NN / 32), dim3(32, 32)>>>(adj);
    gat_main_kernel<<<dim3(NN / 64, HH, BB), 256>>>(out);
}